// round 1
// baseline (speedup 1.0000x reference)
#include <cuda_runtime.h>

#define NB 65536
#define XDIM 362
#define NACT 3
#define GS 19

typedef unsigned long long ull;

// ---------- scratch (static __device__, no allocation) ----------
__device__ int   g_cnt[NACT];
__device__ int   g_perm[NACT * NB];
__device__ int   g_ptr[NB];
__device__ float g_att[NB * 6];

// ---------- packed f32x2 helpers ----------
__device__ __forceinline__ ull ffma2(ull a, ull b, ull c) {
    ull d;
    asm("fma.rn.f32x2 %0, %1, %2, %3;" : "=l"(d) : "l"(a), "l"(b), "l"(c));
    return d;
}
__device__ __forceinline__ ull pack2(float lo, float hi) {
    ull d;
    asm("mov.b64 %0, {%1, %2};" : "=l"(d) : "f"(lo), "f"(hi));
    return d;
}
__device__ __forceinline__ void unpack2(ull v, float& lo, float& hi) {
    asm("mov.b64 {%0, %1}, %2;" : "=f"(lo), "=f"(hi) : "l"(v));
}
__device__ __forceinline__ ull relu2(ull v) {
    float lo, hi;
    unpack2(v, lo, hi);
    return pack2(fmaxf(lo, 0.0f), fmaxf(hi, 0.0f));
}
__device__ __forceinline__ int clampi(int v) { return min(max(v, 1), XDIM - 1); }

// ---------- K0: zero counters ----------
__global__ void k_zero() {
    if (threadIdx.x < NACT) g_cnt[threadIdx.x] = 0;
}

// ---------- K1: argmax + copy + gather + action bucketing ----------
__global__ void __launch_bounds__(256) k_prep(const float* __restrict__ x,
                                              const int* __restrict__ act,
                                              float* __restrict__ out) {
    const int warp = threadIdx.x >> 5;
    const int lane = threadIdx.x & 31;
    const int row = blockIdx.x * 8 + warp;

    const float2* __restrict__ xr = (const float2*)(x + (size_t)row * XDIM);
    float2* __restrict__ orow = (float2*)(out + (size_t)row * XDIM);

    float bv = -3.4e38f;
    int bi = 0;
    // 362 floats = 181 float2 (row byte stride 1448 is 8B aligned)
    #pragma unroll
    for (int it = 0; it < 6; ++it) {
        int i = it * 32 + lane;
        if (i < 181) {
            float2 v = xr[i];
            orow[i] = v;  // fused copy of batch_x into out
            int c0 = 2 * i;
            if (v.x > bv) { bv = v.x; bi = c0; }
            if (v.y > bv) { bv = v.y; bi = c0 + 1; }
        }
    }
    // warp argmax, first-index-wins on ties
    #pragma unroll
    for (int off = 16; off; off >>= 1) {
        float ov = __shfl_down_sync(0xffffffffu, bv, off);
        int oi = __shfl_down_sync(0xffffffffu, bi, off);
        if (ov > bv || (ov == bv && oi < bi)) { bv = ov; bi = oi; }
    }
    const int ptr = __shfl_sync(0xffffffffu, bi, 0);

    if (lane < 6) {
        int idx;
        if (lane == 0) idx = 0;
        else if (lane == 1) idx = ptr;
        else if (lane == 2) idx = clampi(ptr - GS);
        else if (lane == 3) idx = clampi(ptr + GS);
        else if (lane == 4) idx = clampi(ptr - 1);
        else idx = clampi(ptr + 1);
        g_att[row * 6 + lane] = x[(size_t)row * XDIM + idx];
    }
    if (lane == 0) {
        g_ptr[row] = ptr;
        int a = act[row];
        int pos = atomicAdd(&g_cnt[a], 1);
        g_perm[a * NB + pos] = row;
    }
}

// ---------- K2: fused MLP (f32x2) + scatter ----------
// shared layout (floats)
#define W2T_OFF 0        // [100][104] transposed chunk of W2 (k consecutive)
#define W3_OFF 10400     // [100][104] chunk of W3 (m consecutive)
#define W1_OFF 20800     // [6][104]
#define B1_OFF 21424
#define B2_OFF 21524
#define B3_OFF 21924
#define W4_OFF 22024
#define B4_OFF 22624
#define SMEM_FLOATS 22632

extern __shared__ float sm[];

__global__ void __launch_bounds__(256, 1) k_mlp(
    const float* __restrict__ W1, const float* __restrict__ b1,
    const float* __restrict__ W2, const float* __restrict__ b2,
    const float* __restrict__ W3, const float* __restrict__ b3,
    const float* __restrict__ W4, const float* __restrict__ b4,
    float* __restrict__ out)
{
    const int a = blockIdx.y;
    const int cnt = g_cnt[a];
    const int base = blockIdx.x * 256;
    if (base >= cnt) return;
    const int tid = threadIdx.x;

    // one-time small weights
    for (int t = tid; t < 600; t += 256)
        sm[W1_OFF + (t / 100) * 104 + (t % 100)] = W1[a * 600 + t];
    for (int t = tid; t < 100; t += 256) sm[B1_OFF + t] = b1[a * 100 + t];
    for (int t = tid; t < 400; t += 256) sm[B2_OFF + t] = b2[a * 400 + t];
    for (int t = tid; t < 100; t += 256) sm[B3_OFF + t] = b3[a * 100 + t];
    for (int t = tid; t < 600; t += 256) sm[W4_OFF + t] = W4[a * 600 + t];
    if (tid < 6) sm[B4_OFF + tid] = b4[a * 6 + tid];
    // chunk 0 of W2 (transposed) and W3
    for (int t = tid; t < 10000; t += 256) {
        int k = t / 100, j = t % 100;
        sm[W2T_OFF + j * 104 + k] = W2[a * 40000 + k * 400 + j];
    }
    for (int t = tid; t < 10000; t += 256) {
        int j = t / 100, m = t % 100;
        sm[W3_OFF + j * 104 + m] = W3[a * 40000 + j * 100 + m];
    }
    __syncthreads();

    const int gidx = base + tid;
    const bool active = gidx < cnt;
    const int s = active ? g_perm[a * NB + gidx] : 0;

    float att[6];
    ull h1p[50];   // packed h1 pairs {h1[2k], h1[2k+1]}
    ull acc3[50];  // packed layer-3 accumulators

    if (active) {
        ull attp[6];
        #pragma unroll
        for (int k = 0; k < 6; ++k) {
            att[k] = g_att[s * 6 + k];
            attp[k] = pack2(att[k], att[k]);
        }
        const ull* sb1 = (const ull*)(sm + B1_OFF);
        #pragma unroll
        for (int mp = 0; mp < 50; ++mp) h1p[mp] = sb1[mp];
        #pragma unroll
        for (int k = 0; k < 6; ++k) {
            const ull* w1p = (const ull*)(sm + W1_OFF + k * 104);
            #pragma unroll
            for (int mp = 0; mp < 50; ++mp)
                h1p[mp] = ffma2(attp[k], w1p[mp], h1p[mp]);
        }
        #pragma unroll
        for (int mp = 0; mp < 50; ++mp) h1p[mp] = relu2(h1p[mp]);
        const ull* sb3 = (const ull*)(sm + B3_OFF);
        #pragma unroll
        for (int mp = 0; mp < 50; ++mp) acc3[mp] = sb3[mp];
    }

    // layers 2+3 fused over j, 4 chunks of 100 j's
    #pragma unroll 1
    for (int c = 0; c < 4; ++c) {
        if (c > 0) {
            __syncthreads();
            for (int t = tid; t < 10000; t += 256) {
                int k = t / 100, j = t % 100;
                sm[W2T_OFF + j * 104 + k] = W2[a * 40000 + k * 400 + c * 100 + j];
            }
            for (int t = tid; t < 10000; t += 256) {
                int j = t / 100, m = t % 100;
                sm[W3_OFF + j * 104 + m] = W3[a * 40000 + (c * 100 + j) * 100 + m];
            }
            __syncthreads();
        }
        if (active) {
            #pragma unroll 1
            for (int j = 0; j < 100; ++j) {
                const ulonglong2* w2row =
                    (const ulonglong2*)(sm + W2T_OFF + j * 104);
                ull a0 = 0ull, a1 = 0ull;
                #pragma unroll
                for (int q = 0; q < 25; ++q) {
                    ulonglong2 w = w2row[q];
                    a0 = ffma2(h1p[2 * q], w.x, a0);
                    a1 = ffma2(h1p[2 * q + 1], w.y, a1);
                }
                float l0, h0, l1, h1v;
                unpack2(a0, l0, h0);
                unpack2(a1, l1, h1v);
                float h2 = l0 + h0 + l1 + h1v + sm[B2_OFF + c * 100 + j];
                h2 = fmaxf(h2, 0.0f);
                ull h2p = pack2(h2, h2);
                const ulonglong2* w3row =
                    (const ulonglong2*)(sm + W3_OFF + j * 104);
                #pragma unroll
                for (int q = 0; q < 25; ++q) {
                    ulonglong2 w = w3row[q];
                    acc3[2 * q] = ffma2(h2p, w.x, acc3[2 * q]);
                    acc3[2 * q + 1] = ffma2(h2p, w.y, acc3[2 * q + 1]);
                }
            }
        }
    }

    if (!active) return;

    // layer 4 (tiny, scalar fp32)
    float p[6];
    #pragma unroll
    for (int o = 0; o < 6; ++o) p[o] = sm[B4_OFF + o];
    #pragma unroll
    for (int mp = 0; mp < 50; ++mp) {
        float h3a, h3b;
        unpack2(acc3[mp], h3a, h3b);
        h3a = fmaxf(h3a, 0.0f);
        h3b = fmaxf(h3b, 0.0f);
        #pragma unroll
        for (int o = 0; o < 6; ++o) {
            p[o] = fmaf(h3a, sm[W4_OFF + (2 * mp) * 6 + o], p[o]);
            p[o] = fmaf(h3b, sm[W4_OFF + (2 * mp + 1) * 6 + o], p[o]);
        }
    }

    // scatter: out[idx_j] = x[idx_j] + pred[j], j ascending (last wins)
    const int ptr = g_ptr[s];
    int idxs[6];
    idxs[0] = 0;
    idxs[1] = ptr;
    idxs[2] = clampi(ptr - GS);
    idxs[3] = clampi(ptr + GS);
    idxs[4] = clampi(ptr - 1);
    idxs[5] = clampi(ptr + 1);
    float* orow = out + (size_t)s * XDIM;
    #pragma unroll
    for (int j = 0; j < 6; ++j) orow[idxs[j]] = att[j] + p[j];
}

// ---------- launch ----------
extern "C" void kernel_launch(void* const* d_in, const int* in_sizes, int n_in,
                              void* d_out, int out_size) {
    const float* x  = (const float*)d_in[0];
    const float* W1 = (const float*)d_in[1];
    const float* b1 = (const float*)d_in[2];
    const float* W2 = (const float*)d_in[3];
    const float* b2 = (const float*)d_in[4];
    const float* W3 = (const float*)d_in[5];
    const float* b3 = (const float*)d_in[6];
    const float* W4 = (const float*)d_in[7];
    const float* b4 = (const float*)d_in[8];
    const int* act  = (const int*)d_in[9];
    float* out = (float*)d_out;

    cudaFuncSetAttribute(k_mlp, cudaFuncAttributeMaxDynamicSharedMemorySize,
                         SMEM_FLOATS * (int)sizeof(float));

    k_zero<<<1, 32>>>();
    k_prep<<<NB / 8, 256>>>(x, act, out);
    dim3 g2((NB + 255) / 256, NACT);
    k_mlp<<<g2, 256, SMEM_FLOATS * sizeof(float)>>>(W1, b1, W2, b2, W3, b3,
                                                    W4, b4, out);
}